// round 6
// baseline (speedup 1.0000x reference)
#include <cuda_runtime.h>

#define NX 1024
#define NY 1024
#define NB 8
#define CH (NX*NY)
#define XSTRIPS 512
#define NBLOCKS (XSTRIPS*NB)   // 4096

// Physics constants
#define PR     0.71f
#define RA_PR  710.0f
#define HA2_PR 71.0f
#define PR_DA  7.1f
#define DIFF_C 1.6666666666666667f
#define QQ     0.1f
#define DTINV  100.0f
#define NPTS   8388608.0

__device__ double   g_partials[NBLOCKS];
__device__ unsigned g_count = 0;   // atomicInc wraps to 0 -> replay-safe

// x-halo via warp shuffle; warp-boundary lanes patch from global.
__device__ __forceinline__ void halo(float4 c, const float* __restrict__ rowp,
                                     int tid, int lane,
                                     float& lz, float& lw, float& rx, float& ry)
{
    lw = __shfl_up_sync(0xFFFFFFFFu, c.w, 1);
    lz = __shfl_up_sync(0xFFFFFFFFu, c.z, 1);
    rx = __shfl_down_sync(0xFFFFFFFFu, c.x, 1);
    ry = __shfl_down_sync(0xFFFFFFFFu, c.y, 1);
    if (lane == 0 && tid != 0) {
        float2 h = *(const float2*)(rowp + tid * 4 - 2);
        lz = h.x; lw = h.y;
    }
    if (lane == 31 && tid != 255) {
        float2 h = *(const float2*)(rowp + tid * 4 + 4);
        rx = h.x; ry = h.y;
    }
}

// x first+second tgrad for 4 points; E0..E7 = values at x0-2 .. x0+5. (R2-verified)
__device__ __forceinline__ void xderiv(float4 c, float lz, float lw, float rx, float ry,
                                       int tid, float* dx, float* dxx)
{
    float E0 = lz, E1 = lw, E2 = c.x, E3 = c.y, E4 = c.z, E5 = c.w, E6 = rx, E7 = ry;
    if (tid == 0) {
        dx[0]  = E3 - E2;
        dx[1]  = 0.5f * (E4 - E2);
        dxx[0] = 0.5f * E4 - E3 + 0.5f * E2;
        dxx[1] = 0.25f * E5 - 0.75f * E3 + 0.5f * E2;
    } else {
        dx[0]  = 0.5f * (E3 - E1);
        dx[1]  = 0.5f * (E4 - E2);
        dxx[0] = 0.25f * (E4 - 2.0f * E2 + E0);
        dxx[1] = 0.25f * (E5 - 2.0f * E3 + E1);
    }
    if (tid == 255) {
        dx[2]  = 0.5f * (E5 - E3);
        dx[3]  = E5 - E4;
        dxx[2] = 0.5f * E5 - 0.75f * E4 + 0.25f * E2;
        dxx[3] = 0.5f * E5 - E4 + 0.5f * E3;
    } else {
        dx[2]  = 0.5f * (E5 - E3);
        dx[3]  = 0.5f * (E6 - E4);
        dxx[2] = 0.25f * (E6 - 2.0f * E4 + E2);
        dxx[3] = 0.25f * (E7 - 2.0f * E5 + E3);
    }
}

// y-derivative coefficients (5-row form over rows y-2..y+2). (R3/R4-verified)
__device__ __forceinline__ void ycoef(int y, float& s1,
                                      float& c0, float& c1, float& c2, float& c3, float& c4)
{
    s1 = (y == 0 || y == NY - 1) ? 1.0f : 0.5f;
    if      (y == 0)      { c0 = 0;     c1 = 0;     c2 = 0.5f;   c3 = -1.0f; c4 = 0.5f; }
    else if (y == 1)      { c0 = 0;     c1 = 0.5f;  c2 = -0.75f; c3 = 0;     c4 = 0.25f; }
    else if (y == NY - 2) { c0 = 0.25f; c1 = 0;     c2 = -0.75f; c3 = 0.5f;  c4 = 0; }
    else if (y == NY - 1) { c0 = 0.5f;  c1 = -1.0f; c2 = 0.5f;   c3 = 0;     c4 = 0; }
    else                  { c0 = 0.25f; c1 = 0;     c2 = -0.5f;  c3 = 0;     c4 = 0.25f; }
}

__global__ __launch_bounds__(256, 2)
void physics_loss_kernel(const float* __restrict__ fno, const float* __restrict__ fne,
                         float* __restrict__ out)
{
    const int tid  = threadIdx.x;
    const int lane = tid & 31;
    const int y0   = blockIdx.x * 2;
    const int y1   = y0 + 1;
    const int b    = blockIdx.y;
    const int x0   = tid * 4;

    const size_t base = (size_t)b * 4 * CH;
    const float* __restrict__ Uc = fne + base;
    const float* __restrict__ Vc = fne + base + CH;
    const float* __restrict__ Tc = fne + base + 2 * (size_t)CH;
    const float* __restrict__ Pc = fne + base + 3 * (size_t)CH;

    auto ld4 = [&](const float* __restrict__ chp, int y) -> float4 {
        y = max(0, min(y, NY - 1));
        return *(const float4*)(chp + (size_t)y * NX + x0);
    };

    float s1A, a0, a1, a2, a3, a4;
    float s1B, b0, b1, b2, b3, b4;
    ycoef(y0, s1A, a0, a1, a2, a3, a4);
    ycoef(y1, s1B, b0, b1, b2, b3, b4);

    // f_now U,V rows (needed across all sections); T_now loaded in T section
    const size_t roA = (size_t)y0 * NX + x0, roB = (size_t)y1 * NX + x0;
    float4 uoA4 = __ldcs((const float4*)(fno + base + roA));
    float4 uoB4 = __ldcs((const float4*)(fno + base + roB));
    float4 voA4 = __ldcs((const float4*)(fno + base + CH + roA));
    float4 voB4 = __ldcs((const float4*)(fno + base + CH + roB));
    const float* UoA = (const float*)&uoA4; const float* UoB = (const float*)&uoB4;
    const float* VoA = (const float*)&voA4; const float* VoB = (const float*)&voB4;

    float contA[4], contB[4], resxA[4], resxB[4], resyA[4], resyB[4], restA[4], restB[4];

    // ================= U channel =================
    {
        float4 r0 = ld4(Uc, y0 - 2), r1 = ld4(Uc, y0 - 1), r2 = ld4(Uc, y0),
               r3 = ld4(Uc, y1),     r4 = ld4(Uc, y1 + 1), r5 = ld4(Uc, y1 + 2);
        float lz, lw, rx, ry;
        float dxA[4], dxxA[4], dxB[4], dxxB[4];
        halo(r2, Uc + (size_t)y0 * NX, tid, lane, lz, lw, rx, ry);
        xderiv(r2, lz, lw, rx, ry, tid, dxA, dxxA);
        halo(r3, Uc + (size_t)y1 * NX, tid, lane, lz, lw, rx, ry);
        xderiv(r3, lz, lw, rx, ry, tid, dxB, dxxB);
        const float* R0 = (const float*)&r0; const float* R1 = (const float*)&r1;
        const float* R2 = (const float*)&r2; const float* R3 = (const float*)&r3;
        const float* R4 = (const float*)&r4; const float* R5 = (const float*)&r5;
#pragma unroll
        for (int j = 0; j < 4; j++) {
            float UnA = R2[j];
            float dyA  = s1A * (R3[j] - R1[j]);
            float dyyA = a0 * R0[j] + a1 * R1[j] + a2 * R2[j] + a3 * R3[j] + a4 * R4[j];
            contA[j] = dxA[j];
            resxA[j] = (UnA - UoA[j]) * DTINV + UnA * dxA[j] + VoA[j] * dyA
                       - PR * (dxxA[j] + dyyA) + PR_DA * UnA;
            float UnB = R3[j];
            float dyB  = s1B * (R4[j] - R2[j]);
            float dyyB = b0 * R1[j] + b1 * R2[j] + b2 * R3[j] + b3 * R4[j] + b4 * R5[j];
            contB[j] = dxB[j];
            resxB[j] = (UnB - UoB[j]) * DTINV + UnB * dxB[j] + VoB[j] * dyB
                       - PR * (dxxB[j] + dyyB) + PR_DA * UnB;
        }
    }
    // ================= V channel =================
    {
        float4 r0 = ld4(Vc, y0 - 2), r1 = ld4(Vc, y0 - 1), r2 = ld4(Vc, y0),
               r3 = ld4(Vc, y1),     r4 = ld4(Vc, y1 + 1), r5 = ld4(Vc, y1 + 2);
        float lz, lw, rx, ry;
        float dxA[4], dxxA[4], dxB[4], dxxB[4];
        halo(r2, Vc + (size_t)y0 * NX, tid, lane, lz, lw, rx, ry);
        xderiv(r2, lz, lw, rx, ry, tid, dxA, dxxA);
        halo(r3, Vc + (size_t)y1 * NX, tid, lane, lz, lw, rx, ry);
        xderiv(r3, lz, lw, rx, ry, tid, dxB, dxxB);
        const float* R0 = (const float*)&r0; const float* R1 = (const float*)&r1;
        const float* R2 = (const float*)&r2; const float* R3 = (const float*)&r3;
        const float* R4 = (const float*)&r4; const float* R5 = (const float*)&r5;
#pragma unroll
        for (int j = 0; j < 4; j++) {
            float VnA = R2[j];
            float dyA  = s1A * (R3[j] - R1[j]);
            float dyyA = a0 * R0[j] + a1 * R1[j] + a2 * R2[j] + a3 * R3[j] + a4 * R4[j];
            contA[j] += dyA;
            resyA[j] = (VnA - VoA[j]) * DTINV + UoA[j] * dxA[j] + VnA * dyA
                       - PR * (dxxA[j] + dyyA) + (HA2_PR + PR_DA) * VnA;
            float VnB = R3[j];
            float dyB  = s1B * (R4[j] - R2[j]);
            float dyyB = b0 * R1[j] + b1 * R2[j] + b2 * R3[j] + b3 * R4[j] + b4 * R5[j];
            contB[j] += dyB;
            resyB[j] = (VnB - VoB[j]) * DTINV + UoB[j] * dxB[j] + VnB * dyB
                       - PR * (dxxB[j] + dyyB) + (HA2_PR + PR_DA) * VnB;
        }
    }
    // ================= T channel =================
    {
        float4 toA4 = __ldcs((const float4*)(fno + base + 2 * (size_t)CH + roA));
        float4 toB4 = __ldcs((const float4*)(fno + base + 2 * (size_t)CH + roB));
        const float* ToA = (const float*)&toA4; const float* ToB = (const float*)&toB4;
        float4 r0 = ld4(Tc, y0 - 2), r1 = ld4(Tc, y0 - 1), r2 = ld4(Tc, y0),
               r3 = ld4(Tc, y1),     r4 = ld4(Tc, y1 + 1), r5 = ld4(Tc, y1 + 2);
        float lz, lw, rx, ry;
        float dxA[4], dxxA[4], dxB[4], dxxB[4];
        halo(r2, Tc + (size_t)y0 * NX, tid, lane, lz, lw, rx, ry);
        xderiv(r2, lz, lw, rx, ry, tid, dxA, dxxA);
        halo(r3, Tc + (size_t)y1 * NX, tid, lane, lz, lw, rx, ry);
        xderiv(r3, lz, lw, rx, ry, tid, dxB, dxxB);
        const float* R0 = (const float*)&r0; const float* R1 = (const float*)&r1;
        const float* R2 = (const float*)&r2; const float* R3 = (const float*)&r3;
        const float* R4 = (const float*)&r4; const float* R5 = (const float*)&r5;
#pragma unroll
        for (int j = 0; j < 4; j++) {
            float TnA = R2[j];
            float dyA  = s1A * (R3[j] - R1[j]);
            float dyyA = a0 * R0[j] + a1 * R1[j] + a2 * R2[j] + a3 * R3[j] + a4 * R4[j];
            resyA[j] -= RA_PR * TnA;
            restA[j] = (TnA - ToA[j]) * DTINV + UoA[j] * dxA[j] + VoA[j] * dyA
                       - DIFF_C * (dxxA[j] + dyyA) - QQ * TnA;
            float TnB = R3[j];
            float dyB  = s1B * (R4[j] - R2[j]);
            float dyyB = b0 * R1[j] + b1 * R2[j] + b2 * R3[j] + b3 * R4[j] + b4 * R5[j];
            resyB[j] -= RA_PR * TnB;
            restB[j] = (TnB - ToB[j]) * DTINV + UoB[j] * dxB[j] + VoB[j] * dyB
                       - DIFF_C * (dxxB[j] + dyyB) - QQ * TnB;
        }
    }
    // ================= P channel (dx, dy only) =================
    {
        float4 r1 = ld4(Pc, y0 - 1), r2 = ld4(Pc, y0),
               r3 = ld4(Pc, y1),     r4 = ld4(Pc, y1 + 1);
        float lz, lw, rx, ry;
        float dxA[4], dxB[4], dxxT[4];
        halo(r2, Pc + (size_t)y0 * NX, tid, lane, lz, lw, rx, ry);
        xderiv(r2, lz, lw, rx, ry, tid, dxA, dxxT);
        halo(r3, Pc + (size_t)y1 * NX, tid, lane, lz, lw, rx, ry);
        xderiv(r3, lz, lw, rx, ry, tid, dxB, dxxT);
        const float* R1 = (const float*)&r1; const float* R2 = (const float*)&r2;
        const float* R3 = (const float*)&r3; const float* R4 = (const float*)&r4;
#pragma unroll
        for (int j = 0; j < 4; j++) {
            resxA[j] += dxA[j];
            resyA[j] += s1A * (R3[j] - R1[j]);
            resxB[j] += dxB[j];
            resyB[j] += s1B * (R4[j] - R2[j]);
        }
    }

    float acc = 0.0f;
#pragma unroll
    for (int j = 0; j < 4; j++) {
        acc += contA[j] * contA[j] + resxA[j] * resxA[j]
             + resyA[j] * resyA[j] + restA[j] * restA[j];
        acc += contB[j] * contB[j] + resxB[j] * resxB[j]
             + resyB[j] * resyB[j] + restB[j] * restB[j];
    }
    double dacc = (double)acc;

    // block reduction
#pragma unroll
    for (int o = 16; o > 0; o >>= 1)
        dacc += __shfl_xor_sync(0xFFFFFFFFu, dacc, o);

    __shared__ double ws[8];
    __shared__ bool   is_last;
    if (lane == 0) ws[tid >> 5] = dacc;
    __syncthreads();

    const int bid = blockIdx.y * XSTRIPS + blockIdx.x;
    if (tid == 0) {
        double s = 0.0;
#pragma unroll
        for (int k = 0; k < 8; k++) s += ws[k];
        g_partials[bid] = s;
        __threadfence();
        unsigned prev = atomicInc(&g_count, NBLOCKS - 1);  // wraps to 0 on last
        is_last = (prev == NBLOCKS - 1);
    }
    __syncthreads();

    // last block reduces all partials and writes output
    if (is_last) {
        double v = 0.0;
#pragma unroll
        for (int k = 0; k < NBLOCKS / 256; k++)
            v += g_partials[tid + k * 256];
#pragma unroll
        for (int o = 16; o > 0; o >>= 1)
            v += __shfl_xor_sync(0xFFFFFFFFu, v, o);
        if (lane == 0) ws[tid >> 5] = v;
        __syncthreads();
        if (tid == 0) {
            double s = 0.0;
#pragma unroll
            for (int k = 0; k < 8; k++) s += ws[k];
            double t = s * 1e-4 / NPTS;
            if (t < 1e-10) t = 1e-10;
            if (t > 1.0)   t = 1.0;
            out[0] = (float)t;
        }
    }
}

extern "C" void kernel_launch(void* const* d_in, const int* in_sizes, int n_in,
                              void* d_out, int out_size)
{
    const float* f_now  = (const float*)d_in[0];
    const float* f_next = (const float*)d_in[1];

    dim3 grid(XSTRIPS, NB);
    physics_loss_kernel<<<grid, 256>>>(f_now, f_next, (float*)d_out);
}

// round 7
// speedup vs baseline: 1.3200x; 1.3200x over previous
#include <cuda_runtime.h>

#define NX 1024
#define NY 1024
#define NB 8
#define CH (NX*NY)
#define ROWS 4
#define STRIPS (NY/ROWS)        // 256
#define NBLOCKS (STRIPS*NB)     // 2048

// Physics constants
#define PR     0.71f
#define RA_PR  710.0f
#define HA2_PR 71.0f
#define PR_DA  7.1f
#define DIFF_C 1.6666666666666667f
#define QQ     0.1f
#define DTINV  100.0f
#define NPTS   8388608.0

__device__ double   g_partials[NBLOCKS];
__device__ unsigned g_count = 0;   // atomicInc wraps -> graph-replay safe

// x-halo via warp shuffle; warp-boundary lanes patch from global (L1 hit).
__device__ __forceinline__ void halo(float4 c, const float* __restrict__ rowp,
                                     int tid, int lane,
                                     float& lz, float& lw, float& rx, float& ry)
{
    lw = __shfl_up_sync(0xFFFFFFFFu, c.w, 1);
    lz = __shfl_up_sync(0xFFFFFFFFu, c.z, 1);
    rx = __shfl_down_sync(0xFFFFFFFFu, c.x, 1);
    ry = __shfl_down_sync(0xFFFFFFFFu, c.y, 1);
    if (lane == 0 && tid != 0) {
        float2 h = *(const float2*)(rowp + tid * 4 - 2);
        lz = h.x; lw = h.y;
    }
    if (lane == 31 && tid != 255) {
        float2 h = *(const float2*)(rowp + tid * 4 + 4);
        rx = h.x; ry = h.y;
    }
}

// x first+second tgrad for 4 points; E0..E7 = values at x0-2..x0+5. (verified)
__device__ __forceinline__ void xderiv(float4 c, float lz, float lw, float rx, float ry,
                                       int tid, float* dx, float* dxx)
{
    float E0 = lz, E1 = lw, E2 = c.x, E3 = c.y, E4 = c.z, E5 = c.w, E6 = rx, E7 = ry;
    if (tid == 0) {
        dx[0]  = E3 - E2;
        dx[1]  = 0.5f * (E4 - E2);
        dxx[0] = 0.5f * E4 - E3 + 0.5f * E2;
        dxx[1] = 0.25f * E5 - 0.75f * E3 + 0.5f * E2;
    } else {
        dx[0]  = 0.5f * (E3 - E1);
        dx[1]  = 0.5f * (E4 - E2);
        dxx[0] = 0.25f * (E4 - 2.0f * E2 + E0);
        dxx[1] = 0.25f * (E5 - 2.0f * E3 + E1);
    }
    if (tid == 255) {
        dx[2]  = 0.5f * (E5 - E3);
        dx[3]  = E5 - E4;
        dxx[2] = 0.5f * E5 - 0.75f * E4 + 0.25f * E2;
        dxx[3] = 0.5f * E5 - E4 + 0.5f * E3;
    } else {
        dx[2]  = 0.5f * (E5 - E3);
        dx[3]  = 0.5f * (E6 - E4);
        dxx[2] = 0.25f * (E6 - 2.0f * E4 + E2);
        dxx[3] = 0.25f * (E7 - 2.0f * E5 + E3);
    }
}

// dx only (for P channel)
__device__ __forceinline__ void xderiv1(float4 c, float lz, float lw, float rx, float ry,
                                        int tid, float* dx)
{
    float E1 = lw, E2 = c.x, E3 = c.y, E4 = c.z, E5 = c.w, E6 = rx;
    dx[1] = 0.5f * (E4 - E2);
    dx[2] = 0.5f * (E5 - E3);
    dx[0] = (tid == 0)   ? (E3 - E2) : 0.5f * (E3 - E1);
    dx[3] = (tid == 255) ? (E5 - E4) : 0.5f * (E6 - E4);
}

// Full derivative set for one channel row (5 y-row loads; overlap rows are L1 hits)
struct CD { float v[4], dx[4], dxx[4], dy[4], dyy[4]; };

__device__ __forceinline__ void chan(const float* __restrict__ chp,
                                     int tid, int lane, int y, int x0,
                                     int rM, int rP, float s1,
                                     int rA, int rB, float cA, float cC, float cB,
                                     CD& d)
{
    const float* rowp = chp + (size_t)y * NX;
    float4 c  = *(const float4*)(rowp + x0);
    float4 m  = *(const float4*)(chp + (size_t)rM * NX + x0);
    float4 p  = *(const float4*)(chp + (size_t)rP * NX + x0);
    float4 a  = *(const float4*)(chp + (size_t)rA * NX + x0);
    float4 bb = *(const float4*)(chp + (size_t)rB * NX + x0);
    float lz, lw, rx, ry;
    halo(c, rowp, tid, lane, lz, lw, rx, ry);
    xderiv(c, lz, lw, rx, ry, tid, d.dx, d.dxx);
    const float* C  = (const float*)&c;
    const float* M  = (const float*)&m;  const float* P_ = (const float*)&p;
    const float* A  = (const float*)&a;  const float* B_ = (const float*)&bb;
#pragma unroll
    for (int j = 0; j < 4; j++) {
        d.v[j]   = C[j];
        d.dy[j]  = s1 * (P_[j] - M[j]);
        d.dyy[j] = cA * A[j] + cC * C[j] + cB * B_[j];
    }
}

__global__ __launch_bounds__(256, 3)
void physics_loss_kernel(const float* __restrict__ fno, const float* __restrict__ fne,
                         float* __restrict__ out)
{
    const int tid  = threadIdx.x;
    const int lane = tid & 31;
    const int strip = blockIdx.x;
    const int b    = blockIdx.y;
    const int y0   = strip * ROWS;
    const int x0   = tid * 4;

    const size_t base = (size_t)b * 4 * CH;
    const float* __restrict__ Uc = fne + base;
    const float* __restrict__ Vc = fne + base + CH;
    const float* __restrict__ Tc = fne + base + 2 * (size_t)CH;
    const float* __restrict__ Pc = fne + base + 3 * (size_t)CH;

    double dacc = 0.0;

#pragma unroll 1
    for (int y = y0; y < y0 + ROWS; y++) {
        const int   rM = (y > 0) ? y - 1 : 0;
        const int   rP = (y < NY - 1) ? y + 1 : NY - 1;
        const float s1 = (y == 0 || y == NY - 1) ? 1.0f : 0.5f;

        int rA, rB; float cA, cC, cB;
        if      (y == 0)      { rA = 2;      cA = 0.5f;  cC = 0.5f;   rB = 1;      cB = -1.0f; }
        else if (y == 1)      { rA = 0;      cA = 0.5f;  cC = -0.75f; rB = 3;      cB = 0.25f; }
        else if (y == NY - 2) { rA = NY - 4; cA = 0.25f; cC = -0.75f; rB = NY - 1; cB = 0.5f;  }
        else if (y == NY - 1) { rA = NY - 3; cA = 0.5f;  cC = 0.5f;   rB = NY - 2; cB = -1.0f; }
        else                  { rA = y - 2;  cA = 0.25f; cC = -0.5f;  rB = y + 2;  cB = 0.25f; }

        const size_t rowo = (size_t)y * NX + x0;
        float rowacc = 0.0f;

        // ---- P pass: pdx, pdy ----
        float pdx[4], pdy[4];
        {
            const float* rowp = Pc + (size_t)y * NX;
            float4 c = *(const float4*)(rowp + x0);
            float4 m = *(const float4*)(Pc + (size_t)rM * NX + x0);
            float4 p = *(const float4*)(Pc + (size_t)rP * NX + x0);
            float lz, lw, rx, ry;
            halo(c, rowp, tid, lane, lz, lw, rx, ry);
            xderiv1(c, lz, lw, rx, ry, tid, pdx);
            const float* M = (const float*)&m; const float* P_ = (const float*)&p;
#pragma unroll
            for (int j = 0; j < 4; j++) pdy[j] = s1 * (P_[j] - M[j]);
        }

        // f_now U, V (needed across passes)
        float4 uo4 = __ldcs((const float4*)(fno + base + rowo));
        float4 vo4 = __ldcs((const float4*)(fno + base + CH + rowo));
        const float* Uo = (const float*)&uo4;
        const float* Vo = (const float*)&vo4;

        float cont[4], resy[4];

        // ---- U pass: resx done, keep cont ----
        {
            CD d;
            chan(Uc, tid, lane, y, x0, rM, rP, s1, rA, rB, cA, cC, cB, d);
#pragma unroll
            for (int j = 0; j < 4; j++) {
                float Un = d.v[j];
                float resx = (Un - Uo[j]) * DTINV + Un * d.dx[j] + Vo[j] * d.dy[j]
                             + pdx[j] - PR * (d.dxx[j] + d.dyy[j]) + PR_DA * Un;
                rowacc += resx * resx;
                cont[j] = d.dx[j];
            }
        }
        // ---- V pass: cont done, keep resy ----
        {
            CD d;
            chan(Vc, tid, lane, y, x0, rM, rP, s1, rA, rB, cA, cC, cB, d);
#pragma unroll
            for (int j = 0; j < 4; j++) {
                float Vn = d.v[j];
                float cj = cont[j] + d.dy[j];
                rowacc += cj * cj;
                resy[j] = (Vn - Vo[j]) * DTINV + Uo[j] * d.dx[j] + Vn * d.dy[j]
                          + pdy[j] - PR * (d.dxx[j] + d.dyy[j]) + (HA2_PR + PR_DA) * Vn;
            }
        }
        // ---- T pass: resy + rest done ----
        {
            float4 to4 = __ldcs((const float4*)(fno + base + 2 * (size_t)CH + rowo));
            const float* To = (const float*)&to4;
            CD d;
            chan(Tc, tid, lane, y, x0, rM, rP, s1, rA, rB, cA, cC, cB, d);
#pragma unroll
            for (int j = 0; j < 4; j++) {
                float Tn = d.v[j];
                float ry2 = resy[j] - RA_PR * Tn;
                rowacc += ry2 * ry2;
                float rest = (Tn - To[j]) * DTINV + Uo[j] * d.dx[j] + Vo[j] * d.dy[j]
                             - DIFF_C * (d.dxx[j] + d.dyy[j]) - QQ * Tn;
                rowacc += rest * rest;
            }
        }

        dacc += (double)rowacc;
    }

    // block reduction
#pragma unroll
    for (int o = 16; o > 0; o >>= 1)
        dacc += __shfl_xor_sync(0xFFFFFFFFu, dacc, o);

    __shared__ double ws[8];
    __shared__ bool   is_last;
    if (lane == 0) ws[tid >> 5] = dacc;
    __syncthreads();

    const int bid = blockIdx.y * STRIPS + blockIdx.x;
    if (tid == 0) {
        double s = 0.0;
#pragma unroll
        for (int k = 0; k < 8; k++) s += ws[k];
        g_partials[bid] = s;
        __threadfence();
        unsigned prev = atomicInc(&g_count, NBLOCKS - 1);
        is_last = (prev == NBLOCKS - 1);
    }
    __syncthreads();

    if (is_last) {
        double v = 0.0;
#pragma unroll
        for (int k = 0; k < NBLOCKS / 256; k++)
            v += g_partials[tid + k * 256];
#pragma unroll
        for (int o = 16; o > 0; o >>= 1)
            v += __shfl_xor_sync(0xFFFFFFFFu, v, o);
        if (lane == 0) ws[tid >> 5] = v;
        __syncthreads();
        if (tid == 0) {
            double s = 0.0;
#pragma unroll
            for (int k = 0; k < 8; k++) s += ws[k];
            double t = s * 1e-4 / NPTS;
            if (t < 1e-10) t = 1e-10;
            if (t > 1.0)   t = 1.0;
            out[0] = (float)t;
        }
    }
}

extern "C" void kernel_launch(void* const* d_in, const int* in_sizes, int n_in,
                              void* d_out, int out_size)
{
    const float* f_now  = (const float*)d_in[0];
    const float* f_next = (const float*)d_in[1];

    dim3 grid(STRIPS, NB);
    physics_loss_kernel<<<grid, 256>>>(f_now, f_next, (float*)d_out);
}